// round 16
// baseline (speedup 1.0000x reference)
#include <cuda_runtime.h>
#include <cstdint>
#include <math.h>

// ---------------- problem constants ----------------
#define CB   128
#define CN   16
#define CINP 1024
#define CE   512
#define CM   15
#define CT   31
#define CL   30
#define CL2  900
#define MASKV (-9e20f)

// output layout offsets
#define O_RECON 0
#define O_U     2097152
#define O_D     (O_U + 2031616)
#define O_STEP  (O_D + 2031616)
#define O_ENT   (O_STEP + 128)
#define O_CLFP  (O_ENT + 128)
#define O_LBL   (O_CLFP + 7936)
#define O_REINF (O_LBL + 3968)

// ---------------- device scratch ----------------
__device__ float g_u[CB*CT*CE];
__device__ float g_d[CB*CT*CE];
__device__ float g_logits[CB*CL2];
__device__ float g_gum[CM*CB*CL2];
__device__ float g_mgn[CM*CB*CE];
__device__ float g_un[CB*CN*CE];
__device__ float g_tcat[CT*CB*1024];
__device__ float g_w1cat[512*1024];
__device__ float g_bufA[3968*512];
__device__ float g_bufB[30720*512];
__device__ float g_bufC[30720*512];
__device__ float g_polout[30720];
__device__ float g_pairs[CM*CB*1024];
__device__ float g_encclean[CM*CB*CE];
__device__ float g_clfbuf[CM*CB*CE];
__device__ float g_unew[CB*CE];
__device__ float g_recon[CB*CN*CINP];
__device__ float g_clfpred[CB*CT*2];
__device__ int   g_active[CB*CN];
__device__ int   g_actions[CM*CB*2];
__device__ float g_logp[CM*CB];
__device__ float g_rew[CM*CB];
__device__ float g_entropy[CB];
__device__ float g_reinf[CB];
__device__ float g_zerobias[1024];

// ---------------- packed f32x2 helpers ----------------
__device__ __forceinline__ unsigned long long f2pack(float lo, float hi) {
  unsigned long long r;
  asm("mov.b64 %0, {%1, %2};" : "=l"(r) : "f"(lo), "f"(hi));
  return r;
}
__device__ __forceinline__ void f2fma(unsigned long long& d, unsigned long long a, unsigned long long b) {
  asm("fma.rn.f32x2 %0, %1, %2, %0;" : "+l"(d) : "l"(a), "l"(b));
}
__device__ __forceinline__ void f2unpack(unsigned long long v, float& lo, float& hi) {
  asm("mov.b64 {%0, %1}, %2;" : "=f"(lo), "=f"(hi) : "l"(v));
}

// ---------------- threefry2x32 (JAX-exact) ----------------
__host__ __device__ __forceinline__ void tf2x32(uint32_t k0, uint32_t k1,
                                                uint32_t x0, uint32_t x1,
                                                uint32_t* o0, uint32_t* o1) {
  uint32_t ks2 = k0 ^ k1 ^ 0x1BD11BDAu;
  x0 += k0; x1 += k1;
#define TFR(r) { x0 += x1; x1 = (x1 << r) | (x1 >> (32 - r)); x1 ^= x0; }
  TFR(13) TFR(15) TFR(26) TFR(6)
  x0 += k1;  x1 += ks2 + 1u;
  TFR(17) TFR(29) TFR(16) TFR(24)
  x0 += ks2; x1 += k0 + 2u;
  TFR(13) TFR(15) TFR(26) TFR(6)
  x0 += k0;  x1 += k1 + 3u;
  TFR(17) TFR(29) TFR(16) TFR(24)
  x0 += k1;  x1 += ks2 + 4u;
  TFR(13) TFR(15) TFR(26) TFR(6)
  x0 += ks2; x1 += k0 + 5u;
#undef TFR
  *o0 = x0; *o1 = x1;
}

__device__ __forceinline__ float erfinv_f(float x) {
  float w = -log1pf(-x * x);
  float p;
  if (w < 5.f) {
    w -= 2.5f;
    p = 2.81022636e-08f;
    p = fmaf(p, w, 3.43273939e-07f);
    p = fmaf(p, w, -3.5233877e-06f);
    p = fmaf(p, w, -4.39150654e-06f);
    p = fmaf(p, w, 0.00021858087f);
    p = fmaf(p, w, -0.00125372503f);
    p = fmaf(p, w, -0.00417768164f);
    p = fmaf(p, w, 0.246640727f);
    p = fmaf(p, w, 1.50140941f);
  } else {
    w = sqrtf(w) - 3.f;
    p = -0.000200214257f;
    p = fmaf(p, w, 0.000100950558f);
    p = fmaf(p, w, 0.00134934322f);
    p = fmaf(p, w, -0.00367342844f);
    p = fmaf(p, w, 0.00573950773f);
    p = fmaf(p, w, -0.0076224613f);
    p = fmaf(p, w, 0.00943887047f);
    p = fmaf(p, w, 1.00167406f);
    p = fmaf(p, w, 2.83297682f);
  }
  return p * x;
}

__device__ __forceinline__ float bits_to_unit(uint32_t b) {
  return __fadd_rn(__uint_as_float((b >> 9) | 0x3f800000u), -1.0f);
}
__device__ __forceinline__ float bits_to_normal(uint32_t b) {
  float f = bits_to_unit(b);
  const float lo = -0.99999994f;
  float u = fmaxf(lo, __fadd_rn(__fmul_rn(f, 2.0f), lo));
  return __fmul_rn(1.41421356f, erfinv_f(u));
}
__device__ __forceinline__ float bits_to_gumbel(uint32_t b) {
  float f = bits_to_unit(b);
  const float tiny = 1.1754944e-38f;
  float u = fmaxf(tiny, __fadd_rn(f, tiny));
  return -logf(-logf(u));
}

__global__ void k_gen_normals_all() {
  uint32_t idx = blockIdx.x * blockDim.x + threadIdx.x;
  const uint32_t NM = CM * CB * CE;
  const uint32_t NU = CB * CN * CE;
  if (idx >= NM + NU) return;
  uint32_t ka, kb, i;
  float* dst;
  if (idx < NM) {
    uint32_t it = idx / (CB * CE); i = idx % (CB * CE);
    tf2x32(0u, 42u, 0u, 1000u + it, &ka, &kb);
    dst = g_mgn + (size_t)it * CB * CE;
  } else {
    i = idx - NM;
    tf2x32(0u, 42u, 0u, 7u, &ka, &kb);
    dst = g_un;
  }
  uint32_t o0, o1; tf2x32(ka, kb, 0u, i, &o0, &o1);
  dst[i] = __fmul_rn(0.01f, bits_to_normal(o0 ^ o1));
}
__global__ void k_gen_gumbels_all() {
  uint32_t idx = blockIdx.x * blockDim.x + threadIdx.x;
  if (idx >= CM * CB * CL2) return;
  uint32_t it = idx / (CB * CL2), i = idx % (CB * CL2);
  uint32_t ka, kb; tf2x32(0u, 42u, 0u, 100u + it, &ka, &kb);
  uint32_t o0, o1; tf2x32(ka, kb, 0u, i, &o0, &o1);
  g_gum[(size_t)it * CB * CL2 + i] = bits_to_gumbel(o0 ^ o1);
}

// ---------------- templated SGEMM: f32x2 FMA + register-prefetch pipeline ----------------
template<int BM, int BN, int TM, int TN, int ACT>
__global__ __launch_bounds__(256) void sgemm_t(
    const float* __restrict__ A, const float* __restrict__ W,
    const float* __restrict__ bias, float* __restrict__ C,
    int M, int N, int K) {
  constexpr int TX = BN / TN;
  constexpr int TY = BM / TM;
  constexpr int TN2 = TN / 2;
  constexpr int LA = BM * 16 / 256;
  constexpr int LB = BN * 16 / 256;
  static_assert(TX * TY == 256 && (TN % 2) == 0, "bad tile");
  __shared__ float As[16][BM + 4];
  __shared__ float Bs[16][BN + 4];
  int tid = threadIdx.x;
  int tx = tid % TX, ty = tid / TX;
  int bm = blockIdx.y * BM, bn = blockIdx.x * BN;
  unsigned long long accp[TM][TN2];
#pragma unroll
  for (int i = 0; i < TM; i++)
#pragma unroll
    for (int j = 0; j < TN2; j++) accp[i][j] = 0ull;

  float ra[LA], rb[LB];
  // prologue: load first k-tile into registers
#pragma unroll
  for (int i = 0; i < LA; i++) {
    int t = tid + i * 256;
    int m = t >> 4, k = t & 15;
    ra[i] = (bm + m < M) ? A[(size_t)(bm + m) * K + k] : 0.f;
  }
#pragma unroll
  for (int i = 0; i < LB; i++) {
    int t = tid + i * 256;
    int k = t / BN, n = t % BN;
    rb[i] = (bn + n < N) ? W[(size_t)k * N + bn + n] : 0.f;
  }

  for (int k0 = 0; k0 < K; k0 += 16) {
    // commit current tile regs -> smem
#pragma unroll
    for (int i = 0; i < LA; i++) {
      int t = tid + i * 256;
      As[t & 15][t >> 4] = ra[i];
    }
#pragma unroll
    for (int i = 0; i < LB; i++) {
      int t = tid + i * 256;
      Bs[t / BN][t % BN] = rb[i];
    }
    __syncthreads();
    // prefetch next tile (LDGs retire under compute shadow)
    if (k0 + 16 < K) {
#pragma unroll
      for (int i = 0; i < LA; i++) {
        int t = tid + i * 256;
        int m = t >> 4, k = t & 15;
        ra[i] = (bm + m < M) ? A[(size_t)(bm + m) * K + k0 + 16 + k] : 0.f;
      }
#pragma unroll
      for (int i = 0; i < LB; i++) {
        int t = tid + i * 256;
        int k = t / BN, n = t % BN;
        rb[i] = (bn + n < N) ? W[(size_t)(k0 + 16 + k) * N + bn + n] : 0.f;
      }
    }
#pragma unroll
    for (int k = 0; k < 16; k++) {
      unsigned long long aa[TM], bp[TN2];
#pragma unroll
      for (int i = 0; i < TM; i++) {
        float av = As[k][ty * TM + i];
        aa[i] = f2pack(av, av);
      }
#pragma unroll
      for (int j = 0; j < TN2; j++)
        bp[j] = *(const unsigned long long*)&Bs[k][tx * TN + 2 * j];
#pragma unroll
      for (int i = 0; i < TM; i++)
#pragma unroll
        for (int j = 0; j < TN2; j++) f2fma(accp[i][j], aa[i], bp[j]);
    }
    __syncthreads();
  }
#pragma unroll
  for (int i = 0; i < TM; i++) {
    int m = bm + ty * TM + i;
    if (m >= M) continue;
#pragma unroll
    for (int j = 0; j < TN2; j++) {
      float v0, v1;
      f2unpack(accp[i][j], v0, v1);
      int n0 = bn + tx * TN + 2 * j;
      if (n0 < N) {
        float v = v0 + bias[n0];
        if (ACT) v = fmaxf(v, 0.f);
        C[(size_t)m * N + n0] = v;
      }
      if (n0 + 1 < N) {
        float v = v1 + bias[n0 + 1];
        if (ACT) v = fmaxf(v, 0.f);
        C[(size_t)m * N + n0 + 1] = v;
      }
    }
  }
}

// GEMV: out[r] = dot(A[r,:512], w) + b[0]   (pol layer 3)
__global__ void k_gemv512(const float* __restrict__ A, const float* __restrict__ w,
                          const float* __restrict__ b, float* __restrict__ out, int R) {
  int row = blockIdx.x * 8 + (threadIdx.x >> 5);
  if (row >= R) return;
  int lane = threadIdx.x & 31;
  const float* a = A + (size_t)row * 512;
  float s = 0.f;
#pragma unroll
  for (int k = 0; k < 16; k++) s = fmaf(a[lane + k * 32], w[lane + k * 32], s);
#pragma unroll
  for (int o = 16; o; o >>= 1) s += __shfl_xor_sync(0xffffffffu, s, o);
  if (!lane) out[row] = s + b[0];
}
// GEMV with 2 outputs (clf layer 3)
__global__ void k_gemv512_2(const float* __restrict__ A, const float* __restrict__ w,
                            const float* __restrict__ b, float* __restrict__ out, int R) {
  int row = blockIdx.x * 8 + (threadIdx.x >> 5);
  if (row >= R) return;
  int lane = threadIdx.x & 31;
  const float* a = A + (size_t)row * 512;
  float s0 = 0.f, s1 = 0.f;
#pragma unroll
  for (int k = 0; k < 16; k++) {
    float av = a[lane + k * 32];
    s0 = fmaf(av, w[(lane + k * 32) * 2 + 0], s0);
    s1 = fmaf(av, w[(lane + k * 32) * 2 + 1], s1);
  }
#pragma unroll
  for (int o = 16; o; o >>= 1) {
    s0 += __shfl_xor_sync(0xffffffffu, s0, o);
    s1 += __shfl_xor_sync(0xffffffffu, s1, o);
  }
  if (!lane) { out[row * 2] = s0 + b[0]; out[row * 2 + 1] = s1 + b[1]; }
}

// ---------------- misc kernels ----------------
__global__ void k_init() {
  int i = blockIdx.x * blockDim.x + threadIdx.x;
  if (i < CB * CL2) g_logits[i] = MASKV;
  if (i < CB * CN)  g_active[i] = i % CN;
  if (i < CB)       g_entropy[i] = 0.f;
}
__global__ void k_zero_d() {
  int i = blockIdx.x * blockDim.x + threadIdx.x;
  if (i < CB * CT * CE / 4) ((float4*)g_d)[i] = make_float4(0.f, 0.f, 0.f, 0.f);
}
__global__ void k_w1cat(const float* __restrict__ w1) {
  int i = blockIdx.x * blockDim.x + threadIdx.x;
  if (i >= 512 * 1024) return;
  int k = i >> 10, n = i & 1023;
  g_w1cat[i] = (n < 512) ? w1[(size_t)k * 512 + n]
                         : w1[(size_t)(512 + k) * 512 + (n - 512)];
}
__global__ void k_scatter_u() {
  int i = blockIdx.x * blockDim.x + threadIdx.x;
  if (i >= CB * CN * CE) return;
  int b = i / (CN * CE), r = i % (CN * CE);
  int n = r / CE, e = r % CE;
  g_u[(size_t)(b * CT + n) * CE + e] = g_bufB[i] + g_un[i];
}
__global__ void k_gather16() {
  int idx = blockIdx.x * blockDim.x + threadIdx.x;
  if (idx >= CB * CN * CE) return;
  int m = idx >> 9, c = idx & 511;
  int n = m >> 7, b = m & 127;
  g_bufA[idx] = g_u[(size_t)(b * CT + n) * CE + c];
}

__global__ void k_build_h1_0(const float* __restrict__ b1) {
  int idx = blockIdx.x * blockDim.x + threadIdx.x;
  if (idx >= CB * 240 * 128) return;
  int r = idx >> 7, q = idx & 127;
  int b = r / 240, p = r % 240;
  int i = p / 15, t = p % 15;
  int jt = t + (t >= i ? 1 : 0);
  float4 a = *(const float4*)&g_tcat[(size_t)(i * CB + b) * 1024 + 4 * q];
  float4 c = *(const float4*)&g_tcat[(size_t)(jt * CB + b) * 1024 + 512 + 4 * q];
  float4 bb = *(const float4*)&b1[4 * q];
  float4 o;
  o.x = fmaxf(a.x + c.x + bb.x, 0.f);
  o.y = fmaxf(a.y + c.y + bb.y, 0.f);
  o.z = fmaxf(a.z + c.z + bb.z, 0.f);
  o.w = fmaxf(a.w + c.w + bb.w, 0.f);
  *(float4*)&g_bufB[(size_t)r * 512 + 4 * q] = o;
}
__global__ void k_build_h1_loop(int it, const float* __restrict__ b1) {
  int Am1 = 15 - it;
  int nt = 15 + it;
  int half = CB * Am1;
  int idx = blockIdx.x * blockDim.x + threadIdx.x;
  if (idx >= 2 * half * 128) return;
  int r = idx >> 7, q = idx & 127;
  bool fwd = r < half;
  int rr = fwd ? r : r - half;
  int b = rr / Am1, k = rr % Am1;
  int act = g_active[b * CN + k];
  int ttok = fwd ? nt : act;
  int btok = fwd ? act : nt;
  float4 a = *(const float4*)&g_tcat[(size_t)(ttok * CB + b) * 1024 + 4 * q];
  float4 c = *(const float4*)&g_tcat[(size_t)(btok * CB + b) * 1024 + 512 + 4 * q];
  float4 bb = *(const float4*)&b1[4 * q];
  float4 o;
  o.x = fmaxf(a.x + c.x + bb.x, 0.f);
  o.y = fmaxf(a.y + c.y + bb.y, 0.f);
  o.z = fmaxf(a.z + c.z + bb.z, 0.f);
  o.w = fmaxf(a.w + c.w + bb.w, 0.f);
  *(float4*)&g_bufB[(size_t)r * 512 + 4 * q] = o;
}

// ---------------- fused step: sample(+scatter+mask+active) + enc MLP ----------------
// 64 blocks x 512 threads; block handles batches 2*blockIdx and 2*blockIdx+1.
__global__ __launch_bounds__(512) void k_step(
    int it, float corr, float logopt,
    const float* __restrict__ w1, const float* __restrict__ b1,
    const float* __restrict__ w2, const float* __restrict__ b2,
    const float* __restrict__ w3, const float* __restrict__ b3) {
  __shared__ float Ws[16][516];
  __shared__ float X[2][1024];
  __shared__ float Y[2][512];
  __shared__ int   sact[2][2];
  float* sf = (float*)Ws;
  float* sv = sf + 512;
  int*   si = (int*)(sv + 512);

  int tid = threadIdx.x;
  int g = tid >> 8, gtid = tid & 255;
  int bat = blockIdx.x * 2 + g;
  float* l = g_logits + bat * CL2;
  const float* gu = g_gum + (size_t)it * CB * CL2 + bat * CL2;
  float* gsf = sf + g * 256;
  float* gsv = sv + g * 256;
  int*   gsi = si + g * 256;

  // Phase A: scatter polout -> logits
  if (it == 0) {
    for (int p = gtid; p < 240; p += 256) {
      int i = p / 15, t = p % 15;
      int j = t + (t >= i ? 1 : 0);
      l[i * CL + j] = g_polout[bat * 240 + p];
    }
  } else {
    int Am1 = 15 - it, nt = 15 + it, half = CB * Am1;
    for (int k = gtid; k < Am1; k += 256) {
      int act = g_active[bat * CN + k];
      l[nt * CL + act] = g_polout[bat * Am1 + k];
      l[act * CL + nt] = g_polout[half + bat * Am1 + k];
    }
  }
  __syncthreads();

  float lmax = -3.4e38f, best = -3.4e38f; int bidx = 0;
  for (int i = gtid; i < CL2; i += 256) {
    float lv = l[i];
    lmax = fmaxf(lmax, lv);
    float s = gu[i] + lv;
    if (s > best) { best = s; bidx = i; }
  }
  gsf[gtid] = lmax; gsv[gtid] = best; gsi[gtid] = bidx;
  __syncthreads();
  for (int o = 128; o > 0; o >>= 1) {
    if (gtid < o) {
      gsf[gtid] = fmaxf(gsf[gtid], gsf[gtid + o]);
      float ov = gsv[gtid + o]; int oi = gsi[gtid + o];
      if (ov > gsv[gtid] || (ov == gsv[gtid] && oi < gsi[gtid])) { gsv[gtid] = ov; gsi[gtid] = oi; }
    }
    __syncthreads();
  }
  float m = gsf[0];
  int sflat = gsi[0];
  __syncthreads();

  float se = 0.f;
  for (int i = gtid; i < CL2; i += 256) se += expf(l[i] - m);
  gsf[gtid] = se; __syncthreads();
  for (int o = 128; o > 0; o >>= 1) { if (gtid < o) gsf[gtid] += gsf[gtid + o]; __syncthreads(); }
  float sum = gsf[0];
  __syncthreads();

  float es = 0.f;
  for (int i = gtid; i < CL2; i += 256) {
    float p = expf(l[i] - m) / sum;
    float pa = p + 1e-20f;
    es += pa * logf(pa);
  }
  gsf[gtid] = es; __syncthreads();
  for (int o = 128; o > 0; o >>= 1) { if (gtid < o) gsf[gtid] += gsf[gtid + o]; __syncthreads(); }

  if (gtid == 0) {
    g_entropy[bat] += -(gsf[0] - corr) / logopt;
    int s0 = sflat / CL, s1 = sflat % CL;
    sact[g][0] = s0; sact[g][1] = s1;
    g_actions[(it * CB + bat) * 2 + 0] = s0;
    g_actions[(it * CB + bat) * 2 + 1] = s1;
    g_logp[it * CB + bat] = logf(expf(l[sflat] - m) / sum);
  }
  __syncthreads();
  int ss0 = sact[g][0], ss1 = sact[g][1];
  for (int k = gtid; k < 120; k += 256) {
    int which = k / 60, rest = k % 60, rc = rest / 30, j = rest % 30;
    int s = which ? ss1 : ss0;
    if (rc == 0) l[s * CL + j] = MASKV;
    else         l[j * CL + s] = MASKV;
  }
  if (gtid == 0) {
    int A = 16 - it;
    int tmp[CN]; int c = 0;
    for (int k = 0; k < A; k++) {
      int v = g_active[bat * CN + k];
      if (v != ss0 && v != ss1) tmp[c++] = v;
    }
    for (int k = 0; k < c; k++) g_active[bat * CN + k] = tmp[k];
    g_active[bat * CN + c] = CN + it;
  }
  __syncthreads();

  // Phase B: enc MLP on the 2 merge pairs
  int r0 = blockIdx.x * 2;
  int j = tid;
#pragma unroll
  for (int r = 0; r < 2; r++) {
    int b = r0 + r;
    int s0 = sact[r][0];
    int s1 = sact[r][1];
    X[r][tid]       = g_u[(size_t)(b * CT + s0) * CE + tid];
    X[r][512 + tid] = g_u[(size_t)(b * CT + s1) * CE + tid];
  }
  __syncthreads();
#pragma unroll
  for (int r = 0; r < 2; r++) {
    float* dst = &g_pairs[((size_t)it * CB + r0 + r) * 1024];
    dst[tid] = X[r][tid]; dst[512 + tid] = X[r][512 + tid];
  }
  float a0, a1;
  // L1: 1024 -> 512 relu
  a0 = b1[j]; a1 = a0;
  for (int k0 = 0; k0 < 1024; k0 += 16) {
#pragma unroll
    for (int i = 0; i < 4; i++) {
      int idx = tid + i * 512, row = idx >> 7, c4 = (idx & 127) << 2;
      *(float4*)&Ws[row][c4] = *(const float4*)&w1[(size_t)(k0 + row) * 512 + c4];
    }
    __syncthreads();
#pragma unroll
    for (int kk = 0; kk < 16; kk += 4) {
      float4 x0 = *(float4*)&X[0][k0 + kk];
      float4 x1 = *(float4*)&X[1][k0 + kk];
      float w;
      w = Ws[kk + 0][j]; a0 = fmaf(x0.x, w, a0); a1 = fmaf(x1.x, w, a1);
      w = Ws[kk + 1][j]; a0 = fmaf(x0.y, w, a0); a1 = fmaf(x1.y, w, a1);
      w = Ws[kk + 2][j]; a0 = fmaf(x0.z, w, a0); a1 = fmaf(x1.z, w, a1);
      w = Ws[kk + 3][j]; a0 = fmaf(x0.w, w, a0); a1 = fmaf(x1.w, w, a1);
    }
    __syncthreads();
  }
  Y[0][j] = fmaxf(a0, 0.f); Y[1][j] = fmaxf(a1, 0.f);
  __syncthreads();
  // L2: 512 -> 512 relu -> X low
  a0 = b2[j]; a1 = a0;
  for (int k0 = 0; k0 < 512; k0 += 16) {
#pragma unroll
    for (int i = 0; i < 4; i++) {
      int idx = tid + i * 512, row = idx >> 7, c4 = (idx & 127) << 2;
      *(float4*)&Ws[row][c4] = *(const float4*)&w2[(size_t)(k0 + row) * 512 + c4];
    }
    __syncthreads();
#pragma unroll
    for (int kk = 0; kk < 16; kk += 4) {
      float4 x0 = *(float4*)&Y[0][k0 + kk];
      float4 x1 = *(float4*)&Y[1][k0 + kk];
      float w;
      w = Ws[kk + 0][j]; a0 = fmaf(x0.x, w, a0); a1 = fmaf(x1.x, w, a1);
      w = Ws[kk + 1][j]; a0 = fmaf(x0.y, w, a0); a1 = fmaf(x1.y, w, a1);
      w = Ws[kk + 2][j]; a0 = fmaf(x0.z, w, a0); a1 = fmaf(x1.z, w, a1);
      w = Ws[kk + 3][j]; a0 = fmaf(x0.w, w, a0); a1 = fmaf(x1.w, w, a1);
    }
    __syncthreads();
  }
  X[0][j] = fmaxf(a0, 0.f); X[1][j] = fmaxf(a1, 0.f);
  __syncthreads();
  // L3: 512 -> 512, write outputs
  a0 = b3[j]; a1 = a0;
  for (int k0 = 0; k0 < 512; k0 += 16) {
#pragma unroll
    for (int i = 0; i < 4; i++) {
      int idx = tid + i * 512, row = idx >> 7, c4 = (idx & 127) << 2;
      *(float4*)&Ws[row][c4] = *(const float4*)&w3[(size_t)(k0 + row) * 512 + c4];
    }
    __syncthreads();
#pragma unroll
    for (int kk = 0; kk < 16; kk += 4) {
      float4 x0 = *(float4*)&X[0][k0 + kk];
      float4 x1 = *(float4*)&X[1][k0 + kk];
      float w;
      w = Ws[kk + 0][j]; a0 = fmaf(x0.x, w, a0); a1 = fmaf(x1.x, w, a1);
      w = Ws[kk + 1][j]; a0 = fmaf(x0.y, w, a0); a1 = fmaf(x1.y, w, a1);
      w = Ws[kk + 2][j]; a0 = fmaf(x0.z, w, a0); a1 = fmaf(x1.z, w, a1);
      w = Ws[kk + 3][j]; a0 = fmaf(x0.w, w, a0); a1 = fmaf(x1.w, w, a1);
    }
    __syncthreads();
  }
  int nt = CN + it;
#pragma unroll
  for (int r = 0; r < 2; r++) {
    int b = r0 + r;
    float clean = r ? a1 : a0;
    float noisy = clean + g_mgn[((size_t)it * CB + b) * CE + j];
    g_encclean[((size_t)it * CB + b) * CE + j] = clean;
    g_u[(size_t)(b * CT + nt) * CE + j] = noisy;
    g_unew[(size_t)b * CE + j] = noisy;
  }
}

// ---------------- fused dec MLP (unroll): 64 blocks x 2 rows ----------------
__global__ __launch_bounds__(512) void k_dec2(
    int it,
    const float* __restrict__ w1, const float* __restrict__ b1,
    const float* __restrict__ w2, const float* __restrict__ b2,
    const float* __restrict__ w3, const float* __restrict__ b3) {
  __shared__ float Ws[16][516];
  __shared__ float X[2][1024];
  __shared__ float Y[2][512];
  int tid = threadIdx.x;
  int r0 = blockIdx.x * 2;
  int j = tid;
  int tok = CT - 1 - it;
#pragma unroll
  for (int r = 0; r < 2; r++) {
    int b = r0 + r;
    float v = g_d[(size_t)(b * CT + tok) * CE + tid];
    Y[r][tid] = v;
    g_clfbuf[((size_t)it * CB + b) * CE + tid] = v;
  }
  __syncthreads();
  float a0, a1;
  // L1
  a0 = b1[j]; a1 = a0;
  for (int k0 = 0; k0 < 512; k0 += 16) {
#pragma unroll
    for (int i = 0; i < 4; i++) {
      int idx = tid + i * 512, row = idx >> 7, c4 = (idx & 127) << 2;
      *(float4*)&Ws[row][c4] = *(const float4*)&w1[(size_t)(k0 + row) * 512 + c4];
    }
    __syncthreads();
#pragma unroll
    for (int kk = 0; kk < 16; kk += 4) {
      float4 x0 = *(float4*)&Y[0][k0 + kk];
      float4 x1 = *(float4*)&Y[1][k0 + kk];
      float w;
      w = Ws[kk + 0][j]; a0 = fmaf(x0.x, w, a0); a1 = fmaf(x1.x, w, a1);
      w = Ws[kk + 1][j]; a0 = fmaf(x0.y, w, a0); a1 = fmaf(x1.y, w, a1);
      w = Ws[kk + 2][j]; a0 = fmaf(x0.z, w, a0); a1 = fmaf(x1.z, w, a1);
      w = Ws[kk + 3][j]; a0 = fmaf(x0.w, w, a0); a1 = fmaf(x1.w, w, a1);
    }
    __syncthreads();
  }
  X[0][j] = fmaxf(a0, 0.f); X[1][j] = fmaxf(a1, 0.f);
  __syncthreads();
  // L2
  a0 = b2[j]; a1 = a0;
  for (int k0 = 0; k0 < 512; k0 += 16) {
#pragma unroll
    for (int i = 0; i < 4; i++) {
      int idx = tid + i * 512, row = idx >> 7, c4 = (idx & 127) << 2;
      *(float4*)&Ws[row][c4] = *(const float4*)&w2[(size_t)(k0 + row) * 512 + c4];
    }
    __syncthreads();
#pragma unroll
    for (int kk = 0; kk < 16; kk += 4) {
      float4 x0 = *(float4*)&X[0][k0 + kk];
      float4 x1 = *(float4*)&X[1][k0 + kk];
      float w;
      w = Ws[kk + 0][j]; a0 = fmaf(x0.x, w, a0); a1 = fmaf(x1.x, w, a1);
      w = Ws[kk + 1][j]; a0 = fmaf(x0.y, w, a0); a1 = fmaf(x1.y, w, a1);
      w = Ws[kk + 2][j]; a0 = fmaf(x0.z, w, a0); a1 = fmaf(x1.z, w, a1);
      w = Ws[kk + 3][j]; a0 = fmaf(x0.w, w, a0); a1 = fmaf(x1.w, w, a1);
    }
    __syncthreads();
  }
  Y[0][j] = fmaxf(a0, 0.f); Y[1][j] = fmaxf(a1, 0.f);
  __syncthreads();
  // L3: two column halves
  int step = CM - 1 - it;
#pragma unroll
  for (int h = 0; h < 2; h++) {
    int jo = h * 512 + j;
    a0 = b3[jo]; a1 = a0;
    for (int k0 = 0; k0 < 512; k0 += 16) {
#pragma unroll
      for (int i = 0; i < 4; i++) {
        int idx = tid + i * 512, row = idx >> 7, c4 = (idx & 127) << 2;
        *(float4*)&Ws[row][c4] = *(const float4*)&w3[(size_t)(k0 + row) * 1024 + h * 512 + c4];
      }
      __syncthreads();
#pragma unroll
      for (int kk = 0; kk < 16; kk += 4) {
        float4 x0 = *(float4*)&Y[0][k0 + kk];
        float4 x1 = *(float4*)&Y[1][k0 + kk];
        float w;
        w = Ws[kk + 0][j]; a0 = fmaf(x0.x, w, a0); a1 = fmaf(x1.x, w, a1);
        w = Ws[kk + 1][j]; a0 = fmaf(x0.y, w, a0); a1 = fmaf(x1.y, w, a1);
        w = Ws[kk + 2][j]; a0 = fmaf(x0.z, w, a0); a1 = fmaf(x1.z, w, a1);
        w = Ws[kk + 3][j]; a0 = fmaf(x0.w, w, a0); a1 = fmaf(x1.w, w, a1);
      }
      __syncthreads();
    }
#pragma unroll
    for (int r = 0; r < 2; r++) {
      int b = r0 + r;
      int atok = g_actions[(step * CB + b) * 2 + h];
      g_d[(size_t)(b * CT + atok) * CE + j] = r ? a1 : a0;
    }
  }
}

__global__ void k_osl_batch() {
  int row = blockIdx.x;
  int tid = threadIdx.x;
  __shared__ float sf[256];
  const float* p = g_bufA + (size_t)row * 1024;
  const float* q = g_pairs + (size_t)row * 1024;
  float s = 0.f;
  for (int i = tid; i < 1024; i += 256) { float d = p[i] - q[i]; s += d * d; }
  sf[tid] = s; __syncthreads();
  for (int o = 128; o > 0; o >>= 1) { if (tid < o) sf[tid] += sf[tid + o]; __syncthreads(); }
  if (tid == 0) g_rew[row] = -(sf[0] / 1024.f);
}

__global__ void k_copy_active() {
  int i = blockIdx.x * blockDim.x + threadIdx.x;
  if (i >= CB * CE) return;
  int b = i / CE, e = i % CE;
  int a = g_active[b * CN + 0];
  g_d[(size_t)(b * CT + a) * CE + e] = g_u[(size_t)(b * CT + a) * CE + e];
}

__global__ void k_gather_clf() {
  int idx = blockIdx.x * blockDim.x + threadIdx.x;
  if (idx >= 3968 * 512) return;
  int m = idx >> 9, c = idx & 511;
  if (m < 1920) g_bufA[idx] = g_clfbuf[idx];
  else {
    int rr = m - 1920;
    int b = rr >> 4, n = rr & 15;
    g_bufA[idx] = g_d[(size_t)(b * CT + n) * CE + c];
  }
}
// gather d[:, :16] rows into g_pairs (for recon on side stream)
__global__ void k_gather_recon() {
  int idx = blockIdx.x * blockDim.x + threadIdx.x;
  if (idx >= CB * CN * CE) return;
  int m = idx >> 9, c = idx & 511;
  int b = m >> 4, n = m & 15;
  g_pairs[idx] = g_d[(size_t)(b * CT + n) * CE + c];
}
__global__ void k_store_clf() {
  int i = blockIdx.x * blockDim.x + threadIdx.x;
  if (i >= 3968 * 2) return;
  int r = i >> 1, c = i & 1;
  if (r < 1920) {
    int it = r >> 7, b = r & 127;
    g_clfpred[b * (CT * 2) + it * 2 + c] = g_polout[i];
  } else {
    int rr = r - 1920;
    int b = rr >> 4, n = rr & 15;
    g_clfpred[b * (CT * 2) + (30 - n) * 2 + c] = g_polout[i];
  }
}

__global__ void k_rewstats() {
  __shared__ float sh[256];
  __shared__ float s_mean, s_den;
  int tid = threadIdx.x;
  float s = 0.f;
  for (int i = tid; i < CM * CB; i += 256) s += g_rew[i];
  sh[tid] = s; __syncthreads();
  for (int o = 128; o > 0; o >>= 1) { if (tid < o) sh[tid] += sh[tid + o]; __syncthreads(); }
  if (tid == 0) s_mean = sh[0] / (float)(CM * CB);
  __syncthreads();
  float mean = s_mean;
  float v = 0.f;
  for (int i = tid; i < CM * CB; i += 256) { float d = g_rew[i] - mean; v += d * d; }
  sh[tid] = v; __syncthreads();
  for (int o = 128; o > 0; o >>= 1) { if (tid < o) sh[tid] += sh[tid + o]; __syncthreads(); }
  if (tid == 0) s_den = sqrtf(sh[0] / (float)(CM * CB - 1)) + 1e-20f;
  __syncthreads();
  if (tid < CB) {
    float acc = 0.f;
    for (int it = 0; it < CM; it++) {
      float rn = (g_rew[it * CB + tid] - mean) / s_den;
      acc += g_logp[it * CB + tid] * rn;
    }
    g_reinf[tid] = acc;
  }
}

// middle of output (u and d copies) — runs on s2 right after dec chain
__global__ void k_output_mid(float* out) {
  int i = blockIdx.x * blockDim.x + threadIdx.x;
  const int N = O_STEP - O_U;
  if (i >= N) return;
  int gi = O_U + i;
  float v;
  if (gi < O_D) v = g_u[gi - O_U];
  else          v = g_d[gi - O_D];
  out[gi] = v;
}
// the rest of the output
__global__ void k_output_rest(float* out, int out_size) {
  int i = blockIdx.x * blockDim.x + threadIdx.x;
  const int NR = O_U + (out_size - O_STEP);   // recon part + tail part
  if (i >= NR) return;
  int gi = (i < O_U) ? i : (O_STEP + (i - O_U));
  float v = 0.f;
  if (gi < O_U)          v = g_recon[gi];
  else if (gi < O_ENT) {
    int b = gi - O_STEP;
    float s = 0.f;
    for (int it = 0; it < CM; it++) s += -g_rew[it * CB + b];
    v = s / 15.0f;
  }
  else if (gi < O_CLFP)  v = g_entropy[gi - O_ENT] / 15.0f;
  else if (gi < O_LBL)   v = g_clfpred[gi - O_CLFP];
  else if (gi < O_REINF) v = ((gi - O_LBL) % CT) < CM ? 1.0f : 0.0f;
  else if (gi < O_REINF + CB) v = g_reinf[gi - O_REINF];
  out[gi] = v;
}

// ---------------- host side ----------------
static void gemm_s(cudaStream_t st, const float* A, const float* W, const float* b, float* C,
                   int M, int N, int K, int act) {
  if (M >= 8192) {
    dim3 g((N + 127) / 128, (M + 127) / 128);
    if (act) sgemm_t<128,128,8,8,1><<<g, 256, 0, st>>>(A, W, b, C, M, N, K);
    else     sgemm_t<128,128,8,8,0><<<g, 256, 0, st>>>(A, W, b, C, M, N, K);
  } else if (M >= 512) {
    dim3 g((N + 63) / 64, (M + 63) / 64);
    if (act) sgemm_t<64,64,4,4,1><<<g, 256, 0, st>>>(A, W, b, C, M, N, K);
    else     sgemm_t<64,64,4,4,0><<<g, 256, 0, st>>>(A, W, b, C, M, N, K);
  } else {
    dim3 g((N + 63) / 64, (M + 31) / 32);
    if (act) sgemm_t<32,64,2,4,1><<<g, 256, 0, st>>>(A, W, b, C, M, N, K);
    else     sgemm_t<32,64,2,4,0><<<g, 256, 0, st>>>(A, W, b, C, M, N, K);
  }
}
#define gemm(A,W,b,C,M,N,K,act) gemm_s((cudaStream_t)0, A, W, b, C, M, N, K, act)

extern "C" void kernel_launch(void* const* d_in, const int* in_sizes, int n_in,
                              void* d_out, int out_size) {
  static const int exp_ins[29] = {
    2097152, 524288, 512, 524288, 1024,
    524288, 512, 262144, 512, 262144, 512,
    262144, 512, 262144, 512, 524288, 1024,
    262144, 512, 262144, 512, 1024, 2,
    524288, 512, 262144, 512, 512, 1 };
  static const int map_alpha[29] = {
    28, 19, 18, 27, 26,
    15, 12, 16, 13, 17, 14,
     9,  6, 10,  7, 11,  8,
     3,  0,  4,  1,  5,  2,
    23, 20, 24, 21, 25, 22 };
  int map_id[29];
  for (int i = 0; i < 29; i++) map_id[i] = i;
  const int* map = map_id;
  bool insertion_ok = (n_in >= 29);
  if (insertion_ok)
    for (int i = 0; i < 29; i++)
      if (in_sizes[i] != exp_ins[i]) { insertion_ok = false; break; }
  if (!insertion_ok && n_in >= 29) {
    bool alpha_ok = true;
    for (int i = 0; i < 29; i++)
      if (in_sizes[map_alpha[i]] != exp_ins[i]) { alpha_ok = false; break; }
    if (alpha_ok) map = map_alpha;
  }

  const float* x        = (const float*)d_in[map[0]];
  const float* lift_w   = (const float*)d_in[map[1]];
  const float* lift_b   = (const float*)d_in[map[2]];
  const float* unlift_w = (const float*)d_in[map[3]];
  const float* unlift_b = (const float*)d_in[map[4]];
  const float* enc_w1 = (const float*)d_in[map[5]];  const float* enc_b1 = (const float*)d_in[map[6]];
  const float* enc_w2 = (const float*)d_in[map[7]];  const float* enc_b2 = (const float*)d_in[map[8]];
  const float* enc_w3 = (const float*)d_in[map[9]];  const float* enc_b3 = (const float*)d_in[map[10]];
  const float* dec_w1 = (const float*)d_in[map[11]]; const float* dec_b1 = (const float*)d_in[map[12]];
  const float* dec_w2 = (const float*)d_in[map[13]]; const float* dec_b2 = (const float*)d_in[map[14]];
  const float* dec_w3 = (const float*)d_in[map[15]]; const float* dec_b3 = (const float*)d_in[map[16]];
  const float* clf_w1 = (const float*)d_in[map[17]]; const float* clf_b1 = (const float*)d_in[map[18]];
  const float* clf_w2 = (const float*)d_in[map[19]]; const float* clf_b2 = (const float*)d_in[map[20]];
  const float* clf_w3 = (const float*)d_in[map[21]]; const float* clf_b3 = (const float*)d_in[map[22]];
  const float* pol_w1 = (const float*)d_in[map[23]]; const float* pol_b1 = (const float*)d_in[map[24]];
  const float* pol_w2 = (const float*)d_in[map[25]]; const float* pol_b2 = (const float*)d_in[map[26]];
  const float* pol_w3 = (const float*)d_in[map[27]]; const float* pol_b3 = (const float*)d_in[map[28]];

  float *pBufA, *pBufB, *pBufC, *pPolout, *pRecon, *pTcat, *pW1cat, *pUnew, *pEncclean, *pZero, *pPairs;
  cudaGetSymbolAddress((void**)&pBufA, g_bufA);
  cudaGetSymbolAddress((void**)&pBufB, g_bufB);
  cudaGetSymbolAddress((void**)&pBufC, g_bufC);
  cudaGetSymbolAddress((void**)&pPolout, g_polout);
  cudaGetSymbolAddress((void**)&pRecon, g_recon);
  cudaGetSymbolAddress((void**)&pTcat, g_tcat);
  cudaGetSymbolAddress((void**)&pW1cat, g_w1cat);
  cudaGetSymbolAddress((void**)&pUnew, g_unew);
  cudaGetSymbolAddress((void**)&pEncclean, g_encclean);
  cudaGetSymbolAddress((void**)&pZero, g_zerobias);
  cudaGetSymbolAddress((void**)&pPairs, g_pairs);

  static cudaStream_t s2 = nullptr;
  static cudaEvent_t evF1 = nullptr, evJ1 = nullptr, evF2 = nullptr, evJ2 = nullptr,
                     evO = nullptr, evJ3 = nullptr;
  if (!s2) {
    cudaStreamCreateWithFlags(&s2, cudaStreamNonBlocking);
    cudaEventCreateWithFlags(&evF1, cudaEventDisableTiming);
    cudaEventCreateWithFlags(&evJ1, cudaEventDisableTiming);
    cudaEventCreateWithFlags(&evF2, cudaEventDisableTiming);
    cudaEventCreateWithFlags(&evJ2, cudaEventDisableTiming);
    cudaEventCreateWithFlags(&evO,  cudaEventDisableTiming);
    cudaEventCreateWithFlags(&evJ3, cudaEventDisableTiming);
  }

  // ---- fork 1: RNG/init on s2 concurrent with lift GEMM on main ----
  cudaEventRecord(evF1, 0);
  cudaStreamWaitEvent(s2, evF1, 0);
  { int n = CM * CB * CE + CB * CN * CE;
    k_gen_normals_all<<<(n + 255) / 256, 256, 0, s2>>>(); }
  { int n = CM * CB * CL2;
    k_gen_gumbels_all<<<(n + 255) / 256, 256, 0, s2>>>(); }
  k_init<<<(CB * CL2 + 255) / 256, 256, 0, s2>>>();
  k_zero_d<<<(CB * CT * CE / 4 + 255) / 256, 256, 0, s2>>>();
  k_w1cat<<<(512 * 1024 + 255) / 256, 256, 0, s2>>>(pol_w1);
  // main: u = lift(x)
  gemm(x, lift_w, lift_b, pBufB, CB * CN, CE, CINP, 0);
  cudaEventRecord(evJ1, s2);
  cudaStreamWaitEvent(0, evJ1, 0);
  k_scatter_u<<<(CB * CN * CE + 255) / 256, 256>>>();

  // per-token pol L1 projections for the 16 initial tokens
  k_gather16<<<(CB * CN * CE + 255) / 256, 256>>>();
  gemm(pBufA, pW1cat, pZero, pTcat, CB * CN, 1024, CE, 0);

  // initial policy
  k_build_h1_0<<<(CB * 240 * 128 + 255) / 256, 256>>>(pol_b1);
  gemm(pBufB, pol_w2, pol_b2, pBufC, CB * 240, 512, 512, 1);
  k_gemv512<<<(CB * 240 + 7) / 8, 256>>>(pBufC, pol_w3, pol_b3, pPolout, CB * 240);

  // sequential merge loop
  for (int it = 0; it < CM; it++) {
    if (it > 0) {
      int Am1 = 15 - it;
      int rows = 2 * CB * Am1;
      k_build_h1_loop<<<(rows * 128 + 255) / 256, 256>>>(it, pol_b1);
      gemm(pBufB, pol_w2, pol_b2, pBufC, rows, 512, 512, 1);
      k_gemv512<<<(rows + 7) / 8, 256>>>(pBufC, pol_w3, pol_b3, pPolout, rows);
    }
    int A = 16 - it;
    double vn = 1e-20 / (1.0 + 900.0 * 1e-20);
    float corr = (float)((double)(900 - A * (A - 1)) * (vn * log(vn)));
    float logopt = (float)log((double)(A * (A - 1)));
    k_step<<<64, 512>>>(it, corr, logopt, enc_w1, enc_b1, enc_w2, enc_b2, enc_w3, enc_b3);
    if (it < CM - 1)
      gemm(pUnew, pW1cat, pZero, pTcat + (size_t)(CN + it) * CB * 1024, CB, 1024, CE, 0);
  }

  // ---- fork 2: unroll dec2 chain on s2 concurrent with deferred dec batch ----
  cudaEventRecord(evF2, 0);
  cudaStreamWaitEvent(s2, evF2, 0);
  k_copy_active<<<(CB * CE + 255) / 256, 256, 0, s2>>>();
  for (int it = 0; it < CM; it++)
    k_dec2<<<64, 512, 0, s2>>>(it, dec_w1, dec_b1, dec_w2, dec_b2, dec_w3, dec_b3);
  cudaEventRecord(evJ2, s2);
  // main: deferred dec batch for step losses
  gemm(pEncclean, dec_w1, dec_b1, pBufB, CM * CB, 512, 512, 1);
  gemm(pBufB,     dec_w2, dec_b2, pBufC, CM * CB, 512, 512, 1);
  gemm(pBufC,     dec_w3, dec_b3, pBufA, CM * CB, 1024, 512, 0);
  k_osl_batch<<<CM * CB, 256>>>();
  cudaEventRecord(evO, 0);                 // g_pairs free after osl
  cudaStreamWaitEvent(0, evJ2, 0);         // main waits for dec2 chain (clfbuf, d)

  // s2: recon + u/d output copy concurrently with clf chain on main
  cudaStreamWaitEvent(s2, evO, 0);
  k_gather_recon<<<(CB * CN * CE + 255) / 256, 256, 0, s2>>>();
  gemm_s(s2, pPairs, unlift_w, unlift_b, pRecon, CB * CN, CINP, CE, 0);
  { int n = O_STEP - O_U;
    k_output_mid<<<(n + 255) / 256, 256, 0, s2>>>((float*)d_out); }
  cudaEventRecord(evJ3, s2);

  // main: batched clf on [mgd rows ; d[:, :16]]
  k_gather_clf<<<(3968 * 512 + 255) / 256, 256>>>();
  gemm(pBufA, clf_w1, clf_b1, pBufB, 3968, 512, 512, 1);
  gemm(pBufB, clf_w2, clf_b2, pBufC, 3968, 512, 512, 1);
  k_gemv512_2<<<(3968 + 7) / 8, 256>>>(pBufC, clf_w3, clf_b3, pPolout, 3968);
  k_store_clf<<<(3968 * 2 + 255) / 256, 256>>>();

  k_rewstats<<<1, 256>>>();
  cudaStreamWaitEvent(0, evJ3, 0);
  { int nr = O_U + (out_size - O_STEP);
    k_output_rest<<<(nr + 255) / 256, 256>>>((float*)d_out, out_size); }
}

// round 17
// speedup vs baseline: 1.0090x; 1.0090x over previous
#include <cuda_runtime.h>
#include <cstdint>
#include <math.h>

// ---------------- problem constants ----------------
#define CB   128
#define CN   16
#define CINP 1024
#define CE   512
#define CM   15
#define CT   31
#define CL   30
#define CL2  900
#define MASKV (-9e20f)

// output layout offsets
#define O_RECON 0
#define O_U     2097152
#define O_D     (O_U + 2031616)
#define O_STEP  (O_D + 2031616)
#define O_ENT   (O_STEP + 128)
#define O_CLFP  (O_ENT + 128)
#define O_LBL   (O_CLFP + 7936)
#define O_REINF (O_LBL + 3968)

// ---------------- device scratch ----------------
__device__ float g_u[CB*CT*CE];
__device__ float g_d[CB*CT*CE];
__device__ float g_logits[CB*CL2];
__device__ float g_gum[CM*CB*CL2];
__device__ float g_mgn[CM*CB*CE];
__device__ float g_un[CB*CN*CE];
__device__ float g_tcat[CT*CB*1024];
__device__ float g_w1cat[512*1024];
__device__ float g_bufA[3968*512];
__device__ float g_bufB[30720*512];
__device__ float g_bufC[30720*512];
__device__ float g_polout[30720];
__device__ float g_pairs[CM*CB*1024];
__device__ float g_encclean[CM*CB*CE];
__device__ float g_clfbuf[CM*CB*CE];
__device__ float g_unew[CB*CE];
__device__ float g_recon[CB*CN*CINP];
__device__ float g_clfpred[CB*CT*2];
__device__ int   g_active[CB*CN];
__device__ int   g_actions[CM*CB*2];
__device__ float g_logp[CM*CB];
__device__ float g_rew[CM*CB];
__device__ float g_entropy[CB];
__device__ float g_reinf[CB];
__device__ float g_zerobias[1024];

// ---------------- packed f32x2 helpers ----------------
__device__ __forceinline__ unsigned long long f2pack(float lo, float hi) {
  unsigned long long r;
  asm("mov.b64 %0, {%1, %2};" : "=l"(r) : "f"(lo), "f"(hi));
  return r;
}
__device__ __forceinline__ void f2fma(unsigned long long& d, unsigned long long a, unsigned long long b) {
  asm("fma.rn.f32x2 %0, %1, %2, %0;" : "+l"(d) : "l"(a), "l"(b));
}
__device__ __forceinline__ void f2unpack(unsigned long long v, float& lo, float& hi) {
  asm("mov.b64 {%0, %1}, %2;" : "=f"(lo), "=f"(hi) : "l"(v));
}

// ---------------- threefry2x32 (JAX-exact) ----------------
__host__ __device__ __forceinline__ void tf2x32(uint32_t k0, uint32_t k1,
                                                uint32_t x0, uint32_t x1,
                                                uint32_t* o0, uint32_t* o1) {
  uint32_t ks2 = k0 ^ k1 ^ 0x1BD11BDAu;
  x0 += k0; x1 += k1;
#define TFR(r) { x0 += x1; x1 = (x1 << r) | (x1 >> (32 - r)); x1 ^= x0; }
  TFR(13) TFR(15) TFR(26) TFR(6)
  x0 += k1;  x1 += ks2 + 1u;
  TFR(17) TFR(29) TFR(16) TFR(24)
  x0 += ks2; x1 += k0 + 2u;
  TFR(13) TFR(15) TFR(26) TFR(6)
  x0 += k0;  x1 += k1 + 3u;
  TFR(17) TFR(29) TFR(16) TFR(24)
  x0 += k1;  x1 += ks2 + 4u;
  TFR(13) TFR(15) TFR(26) TFR(6)
  x0 += ks2; x1 += k0 + 5u;
#undef TFR
  *o0 = x0; *o1 = x1;
}

__device__ __forceinline__ float erfinv_f(float x) {
  float w = -log1pf(-x * x);
  float p;
  if (w < 5.f) {
    w -= 2.5f;
    p = 2.81022636e-08f;
    p = fmaf(p, w, 3.43273939e-07f);
    p = fmaf(p, w, -3.5233877e-06f);
    p = fmaf(p, w, -4.39150654e-06f);
    p = fmaf(p, w, 0.00021858087f);
    p = fmaf(p, w, -0.00125372503f);
    p = fmaf(p, w, -0.00417768164f);
    p = fmaf(p, w, 0.246640727f);
    p = fmaf(p, w, 1.50140941f);
  } else {
    w = sqrtf(w) - 3.f;
    p = -0.000200214257f;
    p = fmaf(p, w, 0.000100950558f);
    p = fmaf(p, w, 0.00134934322f);
    p = fmaf(p, w, -0.00367342844f);
    p = fmaf(p, w, 0.00573950773f);
    p = fmaf(p, w, -0.0076224613f);
    p = fmaf(p, w, 0.00943887047f);
    p = fmaf(p, w, 1.00167406f);
    p = fmaf(p, w, 2.83297682f);
  }
  return p * x;
}

__device__ __forceinline__ float bits_to_unit(uint32_t b) {
  return __fadd_rn(__uint_as_float((b >> 9) | 0x3f800000u), -1.0f);
}
__device__ __forceinline__ float bits_to_normal(uint32_t b) {
  float f = bits_to_unit(b);
  const float lo = -0.99999994f;
  float u = fmaxf(lo, __fadd_rn(__fmul_rn(f, 2.0f), lo));
  return __fmul_rn(1.41421356f, erfinv_f(u));
}
__device__ __forceinline__ float bits_to_gumbel(uint32_t b) {
  float f = bits_to_unit(b);
  const float tiny = 1.1754944e-38f;
  float u = fmaxf(tiny, __fadd_rn(f, tiny));
  return -logf(-logf(u));
}

__global__ void k_gen_normals_all() {
  uint32_t idx = blockIdx.x * blockDim.x + threadIdx.x;
  const uint32_t NM = CM * CB * CE;
  const uint32_t NU = CB * CN * CE;
  if (idx >= NM + NU) return;
  uint32_t ka, kb, i;
  float* dst;
  if (idx < NM) {
    uint32_t it = idx / (CB * CE); i = idx % (CB * CE);
    tf2x32(0u, 42u, 0u, 1000u + it, &ka, &kb);
    dst = g_mgn + (size_t)it * CB * CE;
  } else {
    i = idx - NM;
    tf2x32(0u, 42u, 0u, 7u, &ka, &kb);
    dst = g_un;
  }
  uint32_t o0, o1; tf2x32(ka, kb, 0u, i, &o0, &o1);
  dst[i] = __fmul_rn(0.01f, bits_to_normal(o0 ^ o1));
}
__global__ void k_gen_gumbels_all() {
  uint32_t idx = blockIdx.x * blockDim.x + threadIdx.x;
  if (idx >= CM * CB * CL2) return;
  uint32_t it = idx / (CB * CL2), i = idx % (CB * CL2);
  uint32_t ka, kb; tf2x32(0u, 42u, 0u, 100u + it, &ka, &kb);
  uint32_t o0, o1; tf2x32(ka, kb, 0u, i, &o0, &o1);
  g_gum[(size_t)it * CB * CL2 + i] = bits_to_gumbel(o0 ^ o1);
}

// ---------------- templated SGEMM: f32x2 FMA + register-prefetch pipeline ----------------
template<int BM, int BN, int TM, int TN, int ACT>
__global__ __launch_bounds__(256) void sgemm_t(
    const float* __restrict__ A, const float* __restrict__ W,
    const float* __restrict__ bias, float* __restrict__ C,
    int M, int N, int K) {
  constexpr int TX = BN / TN;
  constexpr int TY = BM / TM;
  constexpr int TN2 = TN / 2;
  constexpr int LA = BM * 16 / 256;
  constexpr int LB = BN * 16 / 256;
  static_assert(TX * TY == 256 && (TN % 2) == 0, "bad tile");
  __shared__ float As[16][BM + 4];
  __shared__ float Bs[16][BN + 4];
  int tid = threadIdx.x;
  int tx = tid % TX, ty = tid / TX;
  int bm = blockIdx.y * BM, bn = blockIdx.x * BN;
  unsigned long long accp[TM][TN2];
#pragma unroll
  for (int i = 0; i < TM; i++)
#pragma unroll
    for (int j = 0; j < TN2; j++) accp[i][j] = 0ull;

  float ra[LA], rb[LB];
#pragma unroll
  for (int i = 0; i < LA; i++) {
    int t = tid + i * 256;
    int m = t >> 4, k = t & 15;
    ra[i] = (bm + m < M) ? A[(size_t)(bm + m) * K + k] : 0.f;
  }
#pragma unroll
  for (int i = 0; i < LB; i++) {
    int t = tid + i * 256;
    int k = t / BN, n = t % BN;
    rb[i] = (bn + n < N) ? W[(size_t)k * N + bn + n] : 0.f;
  }

  for (int k0 = 0; k0 < K; k0 += 16) {
#pragma unroll
    for (int i = 0; i < LA; i++) {
      int t = tid + i * 256;
      As[t & 15][t >> 4] = ra[i];
    }
#pragma unroll
    for (int i = 0; i < LB; i++) {
      int t = tid + i * 256;
      Bs[t / BN][t % BN] = rb[i];
    }
    __syncthreads();
    if (k0 + 16 < K) {
#pragma unroll
      for (int i = 0; i < LA; i++) {
        int t = tid + i * 256;
        int m = t >> 4, k = t & 15;
        ra[i] = (bm + m < M) ? A[(size_t)(bm + m) * K + k0 + 16 + k] : 0.f;
      }
#pragma unroll
      for (int i = 0; i < LB; i++) {
        int t = tid + i * 256;
        int k = t / BN, n = t % BN;
        rb[i] = (bn + n < N) ? W[(size_t)(k0 + 16 + k) * N + bn + n] : 0.f;
      }
    }
#pragma unroll
    for (int k = 0; k < 16; k++) {
      unsigned long long aa[TM], bp[TN2];
#pragma unroll
      for (int i = 0; i < TM; i++) {
        float av = As[k][ty * TM + i];
        aa[i] = f2pack(av, av);
      }
#pragma unroll
      for (int j = 0; j < TN2; j++)
        bp[j] = *(const unsigned long long*)&Bs[k][tx * TN + 2 * j];
#pragma unroll
      for (int i = 0; i < TM; i++)
#pragma unroll
        for (int j = 0; j < TN2; j++) f2fma(accp[i][j], aa[i], bp[j]);
    }
    __syncthreads();
  }
#pragma unroll
  for (int i = 0; i < TM; i++) {
    int m = bm + ty * TM + i;
    if (m >= M) continue;
#pragma unroll
    for (int j = 0; j < TN2; j++) {
      float v0, v1;
      f2unpack(accp[i][j], v0, v1);
      int n0 = bn + tx * TN + 2 * j;
      if (n0 < N) {
        float v = v0 + bias[n0];
        if (ACT) v = fmaxf(v, 0.f);
        C[(size_t)m * N + n0] = v;
      }
      if (n0 + 1 < N) {
        float v = v1 + bias[n0 + 1];
        if (ACT) v = fmaxf(v, 0.f);
        C[(size_t)m * N + n0 + 1] = v;
      }
    }
  }
}

// ---------------- fused policy GEMM: on-the-fly h1, 64x64 tiles, L3-partial epilogue ----
// grid (8, rows/64); writes per-block partial dots to g_bufC[row*8 + colblk].
__global__ __launch_bounds__(256) void sgemm_pol(
    int it, const float* __restrict__ w2, const float* __restrict__ b1v,
    const float* __restrict__ b2v, const float* __restrict__ w3v) {
  __shared__ float As[16][68];
  __shared__ float Bs[16][68];
  __shared__ float b1s[512];
  __shared__ float red[64][17];
  __shared__ int   rTop[64];
  __shared__ int   rBot[64];
  __shared__ float b2s[64];
  __shared__ float w3s[64];
  int tid = threadIdx.x;
  int bm = blockIdx.y * 64, bn = blockIdx.x * 64;
  for (int i = tid; i < 512; i += 256) b1s[i] = b1v[i];
  if (tid < 64) {
    b2s[tid] = b2v[bn + tid];
    w3s[tid] = w3v[bn + tid];
    int m = bm + tid;
    int ttok, btok, b;
    if (it == 0) {
      b = m / 240; int p = m % 240;
      int i2 = p / 15, t = p % 15;
      int jt = t + (t >= i2 ? 1 : 0);
      ttok = i2; btok = jt;
    } else {
      int Am1 = 15 - it, nt = 15 + it, half = CB * Am1;
      bool fwd = m < half; int rr = fwd ? m : m - half;
      b = rr / Am1; int k = rr % Am1;
      int act = g_active[b * CN + k];
      ttok = fwd ? nt : act; btok = fwd ? act : nt;
    }
    rTop[tid] = (ttok * CB + b) * 1024;
    rBot[tid] = (btok * CB + b) * 1024 + 512;
  }
  __syncthreads();

  int tx = tid & 15, ty = tid >> 4;
  unsigned long long accp[4][2];
#pragma unroll
  for (int i = 0; i < 4; i++) { accp[i][0] = 0ull; accp[i][1] = 0ull; }

  float ra[4], rb[4];
#pragma unroll
  for (int i = 0; i < 4; i++) {
    int t = tid + i * 256;
    int m = t >> 4, k = t & 15;
    float v = g_tcat[rTop[m] + k] + g_tcat[rBot[m] + k] + b1s[k];
    ra[i] = fmaxf(v, 0.f);
  }
#pragma unroll
  for (int i = 0; i < 4; i++) {
    int t = tid + i * 256;
    int k = t >> 6, n = t & 63;
    rb[i] = w2[(size_t)k * 512 + bn + n];
  }

  for (int k0 = 0; k0 < 512; k0 += 16) {
#pragma unroll
    for (int i = 0; i < 4; i++) {
      int t = tid + i * 256;
      As[t & 15][t >> 4] = ra[i];
    }
#pragma unroll
    for (int i = 0; i < 4; i++) {
      int t = tid + i * 256;
      Bs[t >> 6][t & 63] = rb[i];
    }
    __syncthreads();
    if (k0 + 16 < 512) {
#pragma unroll
      for (int i = 0; i < 4; i++) {
        int t = tid + i * 256;
        int m = t >> 4, k = t & 15;
        float v = g_tcat[rTop[m] + k0 + 16 + k] + g_tcat[rBot[m] + k0 + 16 + k] + b1s[k0 + 16 + k];
        ra[i] = fmaxf(v, 0.f);
      }
#pragma unroll
      for (int i = 0; i < 4; i++) {
        int t = tid + i * 256;
        int k = t >> 6, n = t & 63;
        rb[i] = w2[(size_t)(k0 + 16 + k) * 512 + bn + n];
      }
    }
#pragma unroll
    for (int k = 0; k < 16; k++) {
      unsigned long long aa[4], bp[2];
#pragma unroll
      for (int i = 0; i < 4; i++) {
        float av = As[k][ty * 4 + i];
        aa[i] = f2pack(av, av);
      }
      bp[0] = *(const unsigned long long*)&Bs[k][tx * 4];
      bp[1] = *(const unsigned long long*)&Bs[k][tx * 4 + 2];
#pragma unroll
      for (int i = 0; i < 4; i++) { f2fma(accp[i][0], aa[i], bp[0]); f2fma(accp[i][1], aa[i], bp[1]); }
    }
    __syncthreads();
  }
  // epilogue: relu(h2) dot w3 -> per-block partial per row
#pragma unroll
  for (int i = 0; i < 4; i++) {
    float partial = 0.f;
#pragma unroll
    for (int j = 0; j < 2; j++) {
      float v0, v1; f2unpack(accp[i][j], v0, v1);
      int n0 = tx * 4 + 2 * j;
      float h0 = fmaxf(v0 + b2s[n0], 0.f);
      float h1 = fmaxf(v1 + b2s[n0 + 1], 0.f);
      partial = fmaf(h0, w3s[n0], partial);
      partial = fmaf(h1, w3s[n0 + 1], partial);
    }
    red[ty * 4 + i][tx] = partial;
  }
  __syncthreads();
  if (tx == 0) {
#pragma unroll
    for (int i = 0; i < 4; i++) {
      int row = ty * 4 + i;
      float s = 0.f;
#pragma unroll
      for (int q = 0; q < 16; q++) s += red[row][q];
      g_bufC[(size_t)(bm + row) * 8 + blockIdx.x] = s;
    }
  }
}
__global__ void k_polsum(int R, const float* __restrict__ b3) {
  int r = blockIdx.x * 256 + threadIdx.x;
  if (r >= R) return;
  float s = 0.f;
#pragma unroll
  for (int q = 0; q < 8; q++) s += g_bufC[(size_t)r * 8 + q];
  g_polout[r] = s + b3[0];
}

// GEMV with 2 outputs (clf layer 3)
__global__ void k_gemv512_2(const float* __restrict__ A, const float* __restrict__ w,
                            const float* __restrict__ b, float* __restrict__ out, int R) {
  int row = blockIdx.x * 8 + (threadIdx.x >> 5);
  if (row >= R) return;
  int lane = threadIdx.x & 31;
  const float* a = A + (size_t)row * 512;
  float s0 = 0.f, s1 = 0.f;
#pragma unroll
  for (int k = 0; k < 16; k++) {
    float av = a[lane + k * 32];
    s0 = fmaf(av, w[(lane + k * 32) * 2 + 0], s0);
    s1 = fmaf(av, w[(lane + k * 32) * 2 + 1], s1);
  }
#pragma unroll
  for (int o = 16; o; o >>= 1) {
    s0 += __shfl_xor_sync(0xffffffffu, s0, o);
    s1 += __shfl_xor_sync(0xffffffffu, s1, o);
  }
  if (!lane) { out[row * 2] = s0 + b[0]; out[row * 2 + 1] = s1 + b[1]; }
}

// ---------------- misc kernels ----------------
__global__ void k_init() {
  int i = blockIdx.x * blockDim.x + threadIdx.x;
  if (i < CB * CL2) g_logits[i] = MASKV;
  if (i < CB * CN)  g_active[i] = i % CN;
  if (i < CB)       g_entropy[i] = 0.f;
}
__global__ void k_zero_d() {
  int i = blockIdx.x * blockDim.x + threadIdx.x;
  if (i < CB * CT * CE / 4) ((float4*)g_d)[i] = make_float4(0.f, 0.f, 0.f, 0.f);
}
__global__ void k_w1cat(const float* __restrict__ w1) {
  int i = blockIdx.x * blockDim.x + threadIdx.x;
  if (i >= 512 * 1024) return;
  int k = i >> 10, n = i & 1023;
  g_w1cat[i] = (n < 512) ? w1[(size_t)k * 512 + n]
                         : w1[(size_t)(512 + k) * 512 + (n - 512)];
}
__global__ void k_scatter_u() {
  int i = blockIdx.x * blockDim.x + threadIdx.x;
  if (i >= CB * CN * CE) return;
  int b = i / (CN * CE), r = i % (CN * CE);
  int n = r / CE, e = r % CE;
  g_u[(size_t)(b * CT + n) * CE + e] = g_bufB[i] + g_un[i];
}
__global__ void k_gather16() {
  int idx = blockIdx.x * blockDim.x + threadIdx.x;
  if (idx >= CB * CN * CE) return;
  int m = idx >> 9, c = idx & 511;
  int n = m >> 7, b = m & 127;
  g_bufA[idx] = g_u[(size_t)(b * CT + n) * CE + c];
}

// ---------------- fused step: sample(+scatter+mask+active) + enc MLP ----------------
__global__ __launch_bounds__(512) void k_step(
    int it, float corr, float logopt,
    const float* __restrict__ w1, const float* __restrict__ b1,
    const float* __restrict__ w2, const float* __restrict__ b2,
    const float* __restrict__ w3, const float* __restrict__ b3) {
  __shared__ float Ws[16][516];
  __shared__ float X[2][1024];
  __shared__ float Y[2][512];
  __shared__ int   sact[2][2];
  float* sf = (float*)Ws;
  float* sv = sf + 512;
  int*   si = (int*)(sv + 512);

  int tid = threadIdx.x;
  int g = tid >> 8, gtid = tid & 255;
  int bat = blockIdx.x * 2 + g;
  float* l = g_logits + bat * CL2;
  const float* gu = g_gum + (size_t)it * CB * CL2 + bat * CL2;
  float* gsf = sf + g * 256;
  float* gsv = sv + g * 256;
  int*   gsi = si + g * 256;

  if (it == 0) {
    for (int p = gtid; p < 240; p += 256) {
      int i = p / 15, t = p % 15;
      int j = t + (t >= i ? 1 : 0);
      l[i * CL + j] = g_polout[bat * 240 + p];
    }
  } else {
    int Am1 = 15 - it, nt = 15 + it, half = CB * Am1;
    for (int k = gtid; k < Am1; k += 256) {
      int act = g_active[bat * CN + k];
      l[nt * CL + act] = g_polout[bat * Am1 + k];
      l[act * CL + nt] = g_polout[half + bat * Am1 + k];
    }
  }
  __syncthreads();

  float lmax = -3.4e38f, best = -3.4e38f; int bidx = 0;
  for (int i = gtid; i < CL2; i += 256) {
    float lv = l[i];
    lmax = fmaxf(lmax, lv);
    float s = gu[i] + lv;
    if (s > best) { best = s; bidx = i; }
  }
  gsf[gtid] = lmax; gsv[gtid] = best; gsi[gtid] = bidx;
  __syncthreads();
  for (int o = 128; o > 0; o >>= 1) {
    if (gtid < o) {
      gsf[gtid] = fmaxf(gsf[gtid], gsf[gtid + o]);
      float ov = gsv[gtid + o]; int oi = gsi[gtid + o];
      if (ov > gsv[gtid] || (ov == gsv[gtid] && oi < gsi[gtid])) { gsv[gtid] = ov; gsi[gtid] = oi; }
    }
    __syncthreads();
  }
  float m = gsf[0];
  int sflat = gsi[0];
  __syncthreads();

  float se = 0.f;
  for (int i = gtid; i < CL2; i += 256) se += expf(l[i] - m);
  gsf[gtid] = se; __syncthreads();
  for (int o = 128; o > 0; o >>= 1) { if (gtid < o) gsf[gtid] += gsf[gtid + o]; __syncthreads(); }
  float sum = gsf[0];
  __syncthreads();

  float es = 0.f;
  for (int i = gtid; i < CL2; i += 256) {
    float p = expf(l[i] - m) / sum;
    float pa = p + 1e-20f;
    es += pa * logf(pa);
  }
  gsf[gtid] = es; __syncthreads();
  for (int o = 128; o > 0; o >>= 1) { if (gtid < o) gsf[gtid] += gsf[gtid + o]; __syncthreads(); }

  if (gtid == 0) {
    g_entropy[bat] += -(gsf[0] - corr) / logopt;
    int s0 = sflat / CL, s1 = sflat % CL;
    sact[g][0] = s0; sact[g][1] = s1;
    g_actions[(it * CB + bat) * 2 + 0] = s0;
    g_actions[(it * CB + bat) * 2 + 1] = s1;
    g_logp[it * CB + bat] = logf(expf(l[sflat] - m) / sum);
  }
  __syncthreads();
  int ss0 = sact[g][0], ss1 = sact[g][1];
  for (int k = gtid; k < 120; k += 256) {
    int which = k / 60, rest = k % 60, rc = rest / 30, j = rest % 30;
    int s = which ? ss1 : ss0;
    if (rc == 0) l[s * CL + j] = MASKV;
    else         l[j * CL + s] = MASKV;
  }
  if (gtid == 0) {
    int A = 16 - it;
    int tmp[CN]; int c = 0;
    for (int k = 0; k < A; k++) {
      int v = g_active[bat * CN + k];
      if (v != ss0 && v != ss1) tmp[c++] = v;
    }
    for (int k = 0; k < c; k++) g_active[bat * CN + k] = tmp[k];
    g_active[bat * CN + c] = CN + it;
  }
  __syncthreads();

  // Phase B: enc MLP
  int r0 = blockIdx.x * 2;
  int j = tid;
#pragma unroll
  for (int r = 0; r < 2; r++) {
    int b = r0 + r;
    int s0 = sact[r][0];
    int s1 = sact[r][1];
    X[r][tid]       = g_u[(size_t)(b * CT + s0) * CE + tid];
    X[r][512 + tid] = g_u[(size_t)(b * CT + s1) * CE + tid];
  }
  __syncthreads();
#pragma unroll
  for (int r = 0; r < 2; r++) {
    float* dst = &g_pairs[((size_t)it * CB + r0 + r) * 1024];
    dst[tid] = X[r][tid]; dst[512 + tid] = X[r][512 + tid];
  }
  float a0, a1;
  a0 = b1[j]; a1 = a0;
  for (int k0 = 0; k0 < 1024; k0 += 16) {
#pragma unroll
    for (int i = 0; i < 4; i++) {
      int idx = tid + i * 512, row = idx >> 7, c4 = (idx & 127) << 2;
      *(float4*)&Ws[row][c4] = *(const float4*)&w1[(size_t)(k0 + row) * 512 + c4];
    }
    __syncthreads();
#pragma unroll
    for (int kk = 0; kk < 16; kk += 4) {
      float4 x0 = *(float4*)&X[0][k0 + kk];
      float4 x1 = *(float4*)&X[1][k0 + kk];
      float w;
      w = Ws[kk + 0][j]; a0 = fmaf(x0.x, w, a0); a1 = fmaf(x1.x, w, a1);
      w = Ws[kk + 1][j]; a0 = fmaf(x0.y, w, a0); a1 = fmaf(x1.y, w, a1);
      w = Ws[kk + 2][j]; a0 = fmaf(x0.z, w, a0); a1 = fmaf(x1.z, w, a1);
      w = Ws[kk + 3][j]; a0 = fmaf(x0.w, w, a0); a1 = fmaf(x1.w, w, a1);
    }
    __syncthreads();
  }
  Y[0][j] = fmaxf(a0, 0.f); Y[1][j] = fmaxf(a1, 0.f);
  __syncthreads();
  a0 = b2[j]; a1 = a0;
  for (int k0 = 0; k0 < 512; k0 += 16) {
#pragma unroll
    for (int i = 0; i < 4; i++) {
      int idx = tid + i * 512, row = idx >> 7, c4 = (idx & 127) << 2;
      *(float4*)&Ws[row][c4] = *(const float4*)&w2[(size_t)(k0 + row) * 512 + c4];
    }
    __syncthreads();
#pragma unroll
    for (int kk = 0; kk < 16; kk += 4) {
      float4 x0 = *(float4*)&Y[0][k0 + kk];
      float4 x1 = *(float4*)&Y[1][k0 + kk];
      float w;
      w = Ws[kk + 0][j]; a0 = fmaf(x0.x, w, a0); a1 = fmaf(x1.x, w, a1);
      w = Ws[kk + 1][j]; a0 = fmaf(x0.y, w, a0); a1 = fmaf(x1.y, w, a1);
      w = Ws[kk + 2][j]; a0 = fmaf(x0.z, w, a0); a1 = fmaf(x1.z, w, a1);
      w = Ws[kk + 3][j]; a0 = fmaf(x0.w, w, a0); a1 = fmaf(x1.w, w, a1);
    }
    __syncthreads();
  }
  X[0][j] = fmaxf(a0, 0.f); X[1][j] = fmaxf(a1, 0.f);
  __syncthreads();
  a0 = b3[j]; a1 = a0;
  for (int k0 = 0; k0 < 512; k0 += 16) {
#pragma unroll
    for (int i = 0; i < 4; i++) {
      int idx = tid + i * 512, row = idx >> 7, c4 = (idx & 127) << 2;
      *(float4*)&Ws[row][c4] = *(const float4*)&w3[(size_t)(k0 + row) * 512 + c4];
    }
    __syncthreads();
#pragma unroll
    for (int kk = 0; kk < 16; kk += 4) {
      float4 x0 = *(float4*)&X[0][k0 + kk];
      float4 x1 = *(float4*)&X[1][k0 + kk];
      float w;
      w = Ws[kk + 0][j]; a0 = fmaf(x0.x, w, a0); a1 = fmaf(x1.x, w, a1);
      w = Ws[kk + 1][j]; a0 = fmaf(x0.y, w, a0); a1 = fmaf(x1.y, w, a1);
      w = Ws[kk + 2][j]; a0 = fmaf(x0.z, w, a0); a1 = fmaf(x1.z, w, a1);
      w = Ws[kk + 3][j]; a0 = fmaf(x0.w, w, a0); a1 = fmaf(x1.w, w, a1);
    }
    __syncthreads();
  }
  int nt = CN + it;
#pragma unroll
  for (int r = 0; r < 2; r++) {
    int b = r0 + r;
    float clean = r ? a1 : a0;
    float noisy = clean + g_mgn[((size_t)it * CB + b) * CE + j];
    g_encclean[((size_t)it * CB + b) * CE + j] = clean;
    g_u[(size_t)(b * CT + nt) * CE + j] = noisy;
    g_unew[(size_t)b * CE + j] = noisy;
  }
}

// ---------------- fused dec MLP (unroll): 64 blocks x 2 rows ----------------
__global__ __launch_bounds__(512) void k_dec2(
    int it,
    const float* __restrict__ w1, const float* __restrict__ b1,
    const float* __restrict__ w2, const float* __restrict__ b2,
    const float* __restrict__ w3, const float* __restrict__ b3) {
  __shared__ float Ws[16][516];
  __shared__ float X[2][1024];
  __shared__ float Y[2][512];
  int tid = threadIdx.x;
  int r0 = blockIdx.x * 2;
  int j = tid;
  int tok = CT - 1 - it;
#pragma unroll
  for (int r = 0; r < 2; r++) {
    int b = r0 + r;
    float v = g_d[(size_t)(b * CT + tok) * CE + tid];
    Y[r][tid] = v;
    g_clfbuf[((size_t)it * CB + b) * CE + tid] = v;
  }
  __syncthreads();
  float a0, a1;
  a0 = b1[j]; a1 = a0;
  for (int k0 = 0; k0 < 512; k0 += 16) {
#pragma unroll
    for (int i = 0; i < 4; i++) {
      int idx = tid + i * 512, row = idx >> 7, c4 = (idx & 127) << 2;
      *(float4*)&Ws[row][c4] = *(const float4*)&w1[(size_t)(k0 + row) * 512 + c4];
    }
    __syncthreads();
#pragma unroll
    for (int kk = 0; kk < 16; kk += 4) {
      float4 x0 = *(float4*)&Y[0][k0 + kk];
      float4 x1 = *(float4*)&Y[1][k0 + kk];
      float w;
      w = Ws[kk + 0][j]; a0 = fmaf(x0.x, w, a0); a1 = fmaf(x1.x, w, a1);
      w = Ws[kk + 1][j]; a0 = fmaf(x0.y, w, a0); a1 = fmaf(x1.y, w, a1);
      w = Ws[kk + 2][j]; a0 = fmaf(x0.z, w, a0); a1 = fmaf(x1.z, w, a1);
      w = Ws[kk + 3][j]; a0 = fmaf(x0.w, w, a0); a1 = fmaf(x1.w, w, a1);
    }
    __syncthreads();
  }
  X[0][j] = fmaxf(a0, 0.f); X[1][j] = fmaxf(a1, 0.f);
  __syncthreads();
  a0 = b2[j]; a1 = a0;
  for (int k0 = 0; k0 < 512; k0 += 16) {
#pragma unroll
    for (int i = 0; i < 4; i++) {
      int idx = tid + i * 512, row = idx >> 7, c4 = (idx & 127) << 2;
      *(float4*)&Ws[row][c4] = *(const float4*)&w2[(size_t)(k0 + row) * 512 + c4];
    }
    __syncthreads();
#pragma unroll
    for (int kk = 0; kk < 16; kk += 4) {
      float4 x0 = *(float4*)&X[0][k0 + kk];
      float4 x1 = *(float4*)&X[1][k0 + kk];
      float w;
      w = Ws[kk + 0][j]; a0 = fmaf(x0.x, w, a0); a1 = fmaf(x1.x, w, a1);
      w = Ws[kk + 1][j]; a0 = fmaf(x0.y, w, a0); a1 = fmaf(x1.y, w, a1);
      w = Ws[kk + 2][j]; a0 = fmaf(x0.z, w, a0); a1 = fmaf(x1.z, w, a1);
      w = Ws[kk + 3][j]; a0 = fmaf(x0.w, w, a0); a1 = fmaf(x1.w, w, a1);
    }
    __syncthreads();
  }
  Y[0][j] = fmaxf(a0, 0.f); Y[1][j] = fmaxf(a1, 0.f);
  __syncthreads();
  int step = CM - 1 - it;
#pragma unroll
  for (int h = 0; h < 2; h++) {
    int jo = h * 512 + j;
    a0 = b3[jo]; a1 = a0;
    for (int k0 = 0; k0 < 512; k0 += 16) {
#pragma unroll
      for (int i = 0; i < 4; i++) {
        int idx = tid + i * 512, row = idx >> 7, c4 = (idx & 127) << 2;
        *(float4*)&Ws[row][c4] = *(const float4*)&w3[(size_t)(k0 + row) * 1024 + h * 512 + c4];
      }
      __syncthreads();
#pragma unroll
      for (int kk = 0; kk < 16; kk += 4) {
        float4 x0 = *(float4*)&Y[0][k0 + kk];
        float4 x1 = *(float4*)&Y[1][k0 + kk];
        float w;
        w = Ws[kk + 0][j]; a0 = fmaf(x0.x, w, a0); a1 = fmaf(x1.x, w, a1);
        w = Ws[kk + 1][j]; a0 = fmaf(x0.y, w, a0); a1 = fmaf(x1.y, w, a1);
        w = Ws[kk + 2][j]; a0 = fmaf(x0.z, w, a0); a1 = fmaf(x1.z, w, a1);
        w = Ws[kk + 3][j]; a0 = fmaf(x0.w, w, a0); a1 = fmaf(x1.w, w, a1);
      }
      __syncthreads();
    }
#pragma unroll
    for (int r = 0; r < 2; r++) {
      int b = r0 + r;
      int atok = g_actions[(step * CB + b) * 2 + h];
      g_d[(size_t)(b * CT + atok) * CE + j] = r ? a1 : a0;
    }
  }
}

__global__ void k_osl_batch() {
  int row = blockIdx.x;
  int tid = threadIdx.x;
  __shared__ float sf[256];
  const float* p = g_bufA + (size_t)row * 1024;
  const float* q = g_pairs + (size_t)row * 1024;
  float s = 0.f;
  for (int i = tid; i < 1024; i += 256) { float d = p[i] - q[i]; s += d * d; }
  sf[tid] = s; __syncthreads();
  for (int o = 128; o > 0; o >>= 1) { if (tid < o) sf[tid] += sf[tid + o]; __syncthreads(); }
  if (tid == 0) g_rew[row] = -(sf[0] / 1024.f);
}

__global__ void k_copy_active() {
  int i = blockIdx.x * blockDim.x + threadIdx.x;
  if (i >= CB * CE) return;
  int b = i / CE, e = i % CE;
  int a = g_active[b * CN + 0];
  g_d[(size_t)(b * CT + a) * CE + e] = g_u[(size_t)(b * CT + a) * CE + e];
}

__global__ void k_gather_clf() {
  int idx = blockIdx.x * blockDim.x + threadIdx.x;
  if (idx >= 3968 * 512) return;
  int m = idx >> 9, c = idx & 511;
  if (m < 1920) g_bufA[idx] = g_clfbuf[idx];
  else {
    int rr = m - 1920;
    int b = rr >> 4, n = rr & 15;
    g_bufA[idx] = g_d[(size_t)(b * CT + n) * CE + c];
  }
}
__global__ void k_gather_recon() {
  int idx = blockIdx.x * blockDim.x + threadIdx.x;
  if (idx >= CB * CN * CE) return;
  int m = idx >> 9, c = idx & 511;
  int b = m >> 4, n = m & 15;
  g_pairs[idx] = g_d[(size_t)(b * CT + n) * CE + c];
}
__global__ void k_store_clf() {
  int i = blockIdx.x * blockDim.x + threadIdx.x;
  if (i >= 3968 * 2) return;
  int r = i >> 1, c = i & 1;
  if (r < 1920) {
    int it = r >> 7, b = r & 127;
    g_clfpred[b * (CT * 2) + it * 2 + c] = g_polout[i];
  } else {
    int rr = r - 1920;
    int b = rr >> 4, n = rr & 15;
    g_clfpred[b * (CT * 2) + (30 - n) * 2 + c] = g_polout[i];
  }
}

__global__ void k_rewstats() {
  __shared__ float sh[256];
  __shared__ float s_mean, s_den;
  int tid = threadIdx.x;
  float s = 0.f;
  for (int i = tid; i < CM * CB; i += 256) s += g_rew[i];
  sh[tid] = s; __syncthreads();
  for (int o = 128; o > 0; o >>= 1) { if (tid < o) sh[tid] += sh[tid + o]; __syncthreads(); }
  if (tid == 0) s_mean = sh[0] / (float)(CM * CB);
  __syncthreads();
  float mean = s_mean;
  float v = 0.f;
  for (int i = tid; i < CM * CB; i += 256) { float d = g_rew[i] - mean; v += d * d; }
  sh[tid] = v; __syncthreads();
  for (int o = 128; o > 0; o >>= 1) { if (tid < o) sh[tid] += sh[tid + o]; __syncthreads(); }
  if (tid == 0) s_den = sqrtf(sh[0] / (float)(CM * CB - 1)) + 1e-20f;
  __syncthreads();
  if (tid < CB) {
    float acc = 0.f;
    for (int it = 0; it < CM; it++) {
      float rn = (g_rew[it * CB + tid] - mean) / s_den;
      acc += g_logp[it * CB + tid] * rn;
    }
    g_reinf[tid] = acc;
  }
}

__global__ void k_output_mid(float* out) {
  int i = blockIdx.x * blockDim.x + threadIdx.x;
  const int N = O_STEP - O_U;
  if (i >= N) return;
  int gi = O_U + i;
  float v;
  if (gi < O_D) v = g_u[gi - O_U];
  else          v = g_d[gi - O_D];
  out[gi] = v;
}
__global__ void k_output_rest(float* out, int out_size) {
  int i = blockIdx.x * blockDim.x + threadIdx.x;
  const int NR = O_U + (out_size - O_STEP);
  if (i >= NR) return;
  int gi = (i < O_U) ? i : (O_STEP + (i - O_U));
  float v = 0.f;
  if (gi < O_U)          v = g_recon[gi];
  else if (gi < O_ENT) {
    int b = gi - O_STEP;
    float s = 0.f;
    for (int it = 0; it < CM; it++) s += -g_rew[it * CB + b];
    v = s / 15.0f;
  }
  else if (gi < O_CLFP)  v = g_entropy[gi - O_ENT] / 15.0f;
  else if (gi < O_LBL)   v = g_clfpred[gi - O_CLFP];
  else if (gi < O_REINF) v = ((gi - O_LBL) % CT) < CM ? 1.0f : 0.0f;
  else if (gi < O_REINF + CB) v = g_reinf[gi - O_REINF];
  out[gi] = v;
}

// ---------------- host side ----------------
static void gemm_s(cudaStream_t st, const float* A, const float* W, const float* b, float* C,
                   int M, int N, int K, int act) {
  if (M >= 8192) {
    dim3 g((N + 127) / 128, (M + 127) / 128);
    if (act) sgemm_t<128,128,8,8,1><<<g, 256, 0, st>>>(A, W, b, C, M, N, K);
    else     sgemm_t<128,128,8,8,0><<<g, 256, 0, st>>>(A, W, b, C, M, N, K);
  } else if (M >= 512) {
    dim3 g((N + 63) / 64, (M + 63) / 64);
    if (act) sgemm_t<64,64,4,4,1><<<g, 256, 0, st>>>(A, W, b, C, M, N, K);
    else     sgemm_t<64,64,4,4,0><<<g, 256, 0, st>>>(A, W, b, C, M, N, K);
  } else {
    dim3 g((N + 63) / 64, (M + 31) / 32);
    if (act) sgemm_t<32,64,2,4,1><<<g, 256, 0, st>>>(A, W, b, C, M, N, K);
    else     sgemm_t<32,64,2,4,0><<<g, 256, 0, st>>>(A, W, b, C, M, N, K);
  }
}
#define gemm(A,W,b,C,M,N,K,act) gemm_s((cudaStream_t)0, A, W, b, C, M, N, K, act)

extern "C" void kernel_launch(void* const* d_in, const int* in_sizes, int n_in,
                              void* d_out, int out_size) {
  static const int exp_ins[29] = {
    2097152, 524288, 512, 524288, 1024,
    524288, 512, 262144, 512, 262144, 512,
    262144, 512, 262144, 512, 524288, 1024,
    262144, 512, 262144, 512, 1024, 2,
    524288, 512, 262144, 512, 512, 1 };
  static const int map_alpha[29] = {
    28, 19, 18, 27, 26,
    15, 12, 16, 13, 17, 14,
     9,  6, 10,  7, 11,  8,
     3,  0,  4,  1,  5,  2,
    23, 20, 24, 21, 25, 22 };
  int map_id[29];
  for (int i = 0; i < 29; i++) map_id[i] = i;
  const int* map = map_id;
  bool insertion_ok = (n_in >= 29);
  if (insertion_ok)
    for (int i = 0; i < 29; i++)
      if (in_sizes[i] != exp_ins[i]) { insertion_ok = false; break; }
  if (!insertion_ok && n_in >= 29) {
    bool alpha_ok = true;
    for (int i = 0; i < 29; i++)
      if (in_sizes[map_alpha[i]] != exp_ins[i]) { alpha_ok = false; break; }
    if (alpha_ok) map = map_alpha;
  }

  const float* x        = (const float*)d_in[map[0]];
  const float* lift_w   = (const float*)d_in[map[1]];
  const float* lift_b   = (const float*)d_in[map[2]];
  const float* unlift_w = (const float*)d_in[map[3]];
  const float* unlift_b = (const float*)d_in[map[4]];
  const float* enc_w1 = (const float*)d_in[map[5]];  const float* enc_b1 = (const float*)d_in[map[6]];
  const float* enc_w2 = (const float*)d_in[map[7]];  const float* enc_b2 = (const float*)d_in[map[8]];
  const float* enc_w3 = (const float*)d_in[map[9]];  const float* enc_b3 = (const float*)d_in[map[10]];
  const float* dec_w1 = (const float*)d_in[map[11]]; const float* dec_b1 = (const float*)d_in[map[12]];
  const float* dec_w2 = (const float*)d_in[map[13]]; const float* dec_b2 = (const float*)d_in[map[14]];
  const float* dec_w3 = (const float*)d_in[map[15]]; const float* dec_b3 = (const float*)d_in[map[16]];
  const float* clf_w1 = (const float*)d_in[map[17]]; const float* clf_b1 = (const float*)d_in[map[18]];
  const float* clf_w2 = (const float*)d_in[map[19]]; const float* clf_b2 = (const float*)d_in[map[20]];
  const float* clf_w3 = (const float*)d_in[map[21]]; const float* clf_b3 = (const float*)d_in[map[22]];
  const float* pol_w1 = (const float*)d_in[map[23]]; const float* pol_b1 = (const float*)d_in[map[24]];
  const float* pol_w2 = (const float*)d_in[map[25]]; const float* pol_b2 = (const float*)d_in[map[26]];
  const float* pol_w3 = (const float*)d_in[map[27]]; const float* pol_b3 = (const float*)d_in[map[28]];

  float *pBufA, *pBufB, *pBufC, *pPolout, *pRecon, *pTcat, *pW1cat, *pUnew, *pEncclean, *pZero, *pPairs;
  cudaGetSymbolAddress((void**)&pBufA, g_bufA);
  cudaGetSymbolAddress((void**)&pBufB, g_bufB);
  cudaGetSymbolAddress((void**)&pBufC, g_bufC);
  cudaGetSymbolAddress((void**)&pPolout, g_polout);
  cudaGetSymbolAddress((void**)&pRecon, g_recon);
  cudaGetSymbolAddress((void**)&pTcat, g_tcat);
  cudaGetSymbolAddress((void**)&pW1cat, g_w1cat);
  cudaGetSymbolAddress((void**)&pUnew, g_unew);
  cudaGetSymbolAddress((void**)&pEncclean, g_encclean);
  cudaGetSymbolAddress((void**)&pZero, g_zerobias);
  cudaGetSymbolAddress((void**)&pPairs, g_pairs);

  static cudaStream_t s2 = nullptr;
  static cudaEvent_t evF1 = nullptr, evJ1 = nullptr, evF2 = nullptr, evJ2 = nullptr,
                     evO = nullptr, evJ3 = nullptr;
  if (!s2) {
    cudaStreamCreateWithFlags(&s2, cudaStreamNonBlocking);
    cudaEventCreateWithFlags(&evF1, cudaEventDisableTiming);
    cudaEventCreateWithFlags(&evJ1, cudaEventDisableTiming);
    cudaEventCreateWithFlags(&evF2, cudaEventDisableTiming);
    cudaEventCreateWithFlags(&evJ2, cudaEventDisableTiming);
    cudaEventCreateWithFlags(&evO,  cudaEventDisableTiming);
    cudaEventCreateWithFlags(&evJ3, cudaEventDisableTiming);
  }

  // ---- fork 1: RNG/init on s2 concurrent with lift GEMM on main ----
  cudaEventRecord(evF1, 0);
  cudaStreamWaitEvent(s2, evF1, 0);
  { int n = CM * CB * CE + CB * CN * CE;
    k_gen_normals_all<<<(n + 255) / 256, 256, 0, s2>>>(); }
  { int n = CM * CB * CL2;
    k_gen_gumbels_all<<<(n + 255) / 256, 256, 0, s2>>>(); }
  k_init<<<(CB * CL2 + 255) / 256, 256, 0, s2>>>();
  k_zero_d<<<(CB * CT * CE / 4 + 255) / 256, 256, 0, s2>>>();
  k_w1cat<<<(512 * 1024 + 255) / 256, 256, 0, s2>>>(pol_w1);
  // main: u = lift(x)
  gemm(x, lift_w, lift_b, pBufB, CB * CN, CE, CINP, 0);
  cudaEventRecord(evJ1, s2);
  cudaStreamWaitEvent(0, evJ1, 0);
  k_scatter_u<<<(CB * CN * CE + 255) / 256, 256>>>();

  // per-token pol L1 projections for the 16 initial tokens
  k_gather16<<<(CB * CN * CE + 255) / 256, 256>>>();
  gemm(pBufA, pW1cat, pZero, pTcat, CB * CN, 1024, CE, 0);

  // sequential merge loop (fused policy GEMM; it=0 is the initial policy)
  for (int it = 0; it < CM; it++) {
    int rows = (it == 0) ? (CB * 240) : (256 * (15 - it));
    sgemm_pol<<<dim3(8, rows / 64), 256>>>(it, pol_w2, pol_b1, pol_b2, pol_w3);
    k_polsum<<<(rows + 255) / 256, 256>>>(rows, pol_b3);
    int A = 16 - it;
    double vn = 1e-20 / (1.0 + 900.0 * 1e-20);
    float corr = (float)((double)(900 - A * (A - 1)) * (vn * log(vn)));
    float logopt = (float)log((double)(A * (A - 1)));
    k_step<<<64, 512>>>(it, corr, logopt, enc_w1, enc_b1, enc_w2, enc_b2, enc_w3, enc_b3);
    if (it < CM - 1)
      gemm(pUnew, pW1cat, pZero, pTcat + (size_t)(CN + it) * CB * 1024, CB, 1024, CE, 0);
  }

  // ---- fork 2: unroll dec2 chain on s2 concurrent with deferred dec batch ----
  cudaEventRecord(evF2, 0);
  cudaStreamWaitEvent(s2, evF2, 0);
  k_copy_active<<<(CB * CE + 255) / 256, 256, 0, s2>>>();
  for (int it = 0; it < CM; it++)
    k_dec2<<<64, 512, 0, s2>>>(it, dec_w1, dec_b1, dec_w2, dec_b2, dec_w3, dec_b3);
  cudaEventRecord(evJ2, s2);
  // main: deferred dec batch for step losses
  gemm(pEncclean, dec_w1, dec_b1, pBufB, CM * CB, 512, 512, 1);
  gemm(pBufB,     dec_w2, dec_b2, pBufC, CM * CB, 512, 512, 1);
  gemm(pBufC,     dec_w3, dec_b3, pBufA, CM * CB, 1024, 512, 0);
  k_osl_batch<<<CM * CB, 256>>>();
  cudaEventRecord(evO, 0);
  cudaStreamWaitEvent(0, evJ2, 0);

  // s2: recon + u/d output copy concurrently with clf chain on main
  cudaStreamWaitEvent(s2, evO, 0);
  k_gather_recon<<<(CB * CN * CE + 255) / 256, 256, 0, s2>>>();
  gemm_s(s2, pPairs, unlift_w, unlift_b, pRecon, CB * CN, CINP, CE, 0);
  { int n = O_STEP - O_U;
    k_output_mid<<<(n + 255) / 256, 256, 0, s2>>>((float*)d_out); }
  cudaEventRecord(evJ3, s2);

  // main: batched clf
  k_gather_clf<<<(3968 * 512 + 255) / 256, 256>>>();
  gemm(pBufA, clf_w1, clf_b1, pBufB, 3968, 512, 512, 1);
  gemm(pBufB, clf_w2, clf_b2, pBufC, 3968, 512, 512, 1);
  k_gemv512_2<<<(3968 + 7) / 8, 256>>>(pBufC, clf_w3, clf_b3, pPolout, 3968);
  k_store_clf<<<(3968 * 2 + 255) / 256, 256>>>();

  k_rewstats<<<1, 256>>>();
  cudaStreamWaitEvent(0, evJ3, 0);
  { int nr = O_U + (out_size - O_STEP);
    k_output_rest<<<(nr + 255) / 256, 256>>>((float*)d_out, out_size); }
}